// round 8
// baseline (speedup 1.0000x reference)
#include <cuda_runtime.h>
#include <cuda_fp16.h>
#include <math.h>
#include <stdint.h>

// ---------------- problem constants ----------------
#define NB     32
#define C_IN   64
#define HW     128
#define OCH    256
#define HASH   8
#define D_A    603
#define KW2    576
#define MPOW   27
#define TSZ    512
#define RADIUS 4.0f
#define UBND   0.99f

// ---------------- device scratch ----------------
__device__ int   g_hist[HASH * TSZ];
__device__ float g_norm[OCH];
__device__ float g_scale;
__device__ int   g_kbuckets[HASH * OCH];
__device__ int   g_voted[HASH];
__device__ int   g_mask[OCH];
__device__ int   g_slot[OCH];    // oc -> compact slot
__device__ int   g_perm[OCH];    // slot -> oc
__device__ int   g_nact;
// permuted fp16 weights in COMPACT slot order: [tap 9][slot 256][128 B]
__device__ uint4 g_wq[18432];    // 294,912 B

// ---------------- helpers ----------------
__device__ __forceinline__ uint32_t smem_u32(const void* p) {
    uint32_t a;
    asm("{ .reg .u64 t; cvta.to.shared.u64 t, %1; cvt.u32.u64 %0, t; }" : "=r"(a) : "l"(p));
    return a;
}
// channel -> byte offset inside a 128B packed row (pair-permuted for mma frags)
__device__ __forceinline__ int cslot(int c) {
    int gg = c >> 4, r = c & 15, q = r >> 1, odd = r & 1;
    int slot = (q < 4) ? (q << 1) : (((q - 4) << 1) | 1);
    return gg * 32 + slot * 4 + odd * 2;
}
__device__ __forceinline__ void mma16816(float* c, uint32_t a0, uint32_t a1,
                                         uint32_t a2, uint32_t a3,
                                         uint32_t b0, uint32_t b1) {
    asm volatile(
        "mma.sync.aligned.m16n8k16.row.col.f32.f16.f16.f32 "
        "{%0,%1,%2,%3}, {%4,%5,%6,%7}, {%8,%9}, {%0,%1,%2,%3};"
        : "+f"(c[0]), "+f"(c[1]), "+f"(c[2]), "+f"(c[3])
        : "r"(a0), "r"(a1), "r"(a2), "r"(a3), "r"(b0), "r"(b1));
}
__device__ __forceinline__ void cp_async16(uint32_t dst, const void* src) {
    asm volatile("{ .reg .u64 gp; cvta.to.global.u64 gp, %1; "
                 "cp.async.cg.shared.global [%0], [gp], 16; }"
                 :: "r"(dst), "l"(src) : "memory");
}
#define CP_COMMIT() asm volatile("cp.async.commit_group;" ::: "memory")
#define CP_WAIT0()  asm volatile("cp.async.wait_group 0;" ::: "memory")

// ---------------- 0: zero hist ----------------
__global__ void zero_hist_kernel() {
    int i = blockIdx.x * blockDim.x + threadIdx.x;
    if (i < HASH * TSZ) g_hist[i] = 0;
}

// ---------------- 1: norms + scale ----------------
__global__ void norms_kernel(const float* __restrict__ w) {
    __shared__ float sn[256];
    int o = threadIdx.x;
    const float* row = w + o * KW2;
    float s = 0.f;
    for (int j = 0; j < KW2; j++) { float v = row[j]; s += v * v; }
    float nrm = sqrtf(s);
    g_norm[o] = nrm;
    sn[o] = nrm;
    __syncthreads();
    for (int st = 128; st > 0; st >>= 1) {
        if (o < st) sn[o] = fmaxf(sn[o], sn[o + st]);
        __syncthreads();
    }
    if (o == 0) g_scale = UBND / sn[0];
}

// ---------------- 2: kernel buckets ----------------
__global__ void kbuckets_kernel(const float* __restrict__ w,
                                const float* __restrict__ a,
                                const float* __restrict__ b) {
    int wid  = (blockIdx.x * blockDim.x + threadIdx.x) >> 5;
    int lane = threadIdx.x & 31;
    if (wid >= HASH * OCH) return;
    int h = wid >> 8, o = wid & 255;
    const float* ar = a + h * D_A;
    const float* wr = w + o * KW2;
    float s = 0.f;
    for (int j = lane; j < KW2; j += 32) s += ar[j] * wr[j];
    #pragma unroll
    for (int off = 16; off; off >>= 1) s += __shfl_down_sync(0xffffffffu, s, off);
    if (lane == 0) {
        float dot = g_scale * s;
        float t = g_scale * g_norm[o];
        #pragma unroll 1
        for (int p = 0; p < MPOW; p++) { t = t * t; dot += ar[KW2 + p] * t; }
        float v = floorf((dot + b[h]) / RADIUS);
        g_kbuckets[h * OCH + o] = (int)fabsf(fmodf(v, (float)TSZ));
    }
}

// ---------------- 3: vote (16x16 tiles) ----------------
#define VT 16
__global__ void vote_kernel(const float* __restrict__ x,
                            const float* __restrict__ a,
                            const float* __restrict__ b) {
    __shared__ float xs[4][VT + 2][20];
    __shared__ float ws[4][9][HASH];
    __shared__ float sb[HASH];
    __shared__ int   shist[HASH * TSZ];

    int tid = threadIdx.x;
    int n = blockIdx.z, x0 = blockIdx.x * VT, y0 = blockIdx.y * VT;

    for (int e = tid; e < HASH * TSZ; e += 256) shist[e] = 0;
    if (tid < HASH) sb[tid] = b[tid];

    int px = tid & 15, py = tid >> 4;
    float acc[HASH];
    #pragma unroll
    for (int h = 0; h < HASH; h++) acc[h] = 0.f;

    for (int c0 = 0; c0 < 68; c0 += 4) {
        __syncthreads();
        for (int e = tid; e < 4 * 18 * 18; e += 256) {
            int c = e / 324, rem = e % 324;
            int ry = rem / 18, rx = rem % 18;
            int cg = c0 + c;
            int gy = y0 - 1 + ry, gx = x0 - 1 + rx;
            float v = 0.f;
            if (cg < 67 && gy >= 0 && gy < HW && gx >= 0 && gx < HW)
                v = (cg < C_IN) ? x[((n * C_IN + cg) * HW + gy) * HW + gx] : 0.5f;
            xs[c][ry][rx] = v;
        }
        for (int e = tid; e < 4 * 9 * HASH; e += 256) {
            int h = e % HASH, rem = e / HASH;
            int c = rem / 9, khw = rem % 9;
            int cg = c0 + c;
            ws[c][khw][h] = (cg < 67) ? a[h * D_A + cg * 9 + khw] : 0.f;
        }
        __syncthreads();
        #pragma unroll
        for (int c = 0; c < 4; c++)
            #pragma unroll
            for (int kh = 0; kh < 3; kh++)
                #pragma unroll
                for (int kw = 0; kw < 3; kw++) {
                    float xv = xs[c][py + kh][px + kw];
                    #pragma unroll
                    for (int h = 0; h < HASH; h++) acc[h] += ws[c][kh * 3 + kw][h] * xv;
                }
    }
    __syncthreads();
    #pragma unroll
    for (int h = 0; h < HASH; h++) {
        float v = floorf((acc[h] + sb[h]) / RADIUS);
        int bk = (int)fabsf(fmodf(v, (float)TSZ));
        atomicAdd(&shist[h * TSZ + bk], 1);
    }
    __syncthreads();
    for (int e = tid; e < HASH * TSZ; e += 256) {
        int v = shist[e];
        if (v) atomicAdd(&g_hist[e], v);
    }
}

// ---------------- 4: argmax ----------------
__global__ void argmax_kernel() {
    int w = threadIdx.x >> 5, lane = threadIdx.x & 31;
    int best = -1, bidx = 0;
    for (int j = lane; j < TSZ; j += 32) {
        int c = g_hist[w * TSZ + j];
        if (c > best) { best = c; bidx = j; }
    }
    #pragma unroll
    for (int off = 16; off; off >>= 1) {
        int ob = __shfl_down_sync(0xffffffffu, best, off);
        int oi = __shfl_down_sync(0xffffffffu, bidx, off);
        if (ob > best || (ob == best && oi < bidx)) { best = ob; bidx = oi; }
    }
    if (lane == 0) g_voted[w] = bidx;
}

// ---------------- 5: mask + compaction (one block, 256 thr) ----------------
__global__ void maskcompact_kernel() {
    __shared__ int sv[HASH];
    __shared__ int scan[256];
    int o = threadIdx.x;
    if (o < HASH) sv[o] = g_voted[o];
    __syncthreads();
    int m = 0;
    #pragma unroll
    for (int h = 0; h < HASH; h++) {
        int kb = g_kbuckets[h * OCH + o];
        #pragma unroll
        for (int j = 0; j < HASH; j++) m |= (kb == sv[j]);
    }
    g_mask[o] = m;
    scan[o] = m;
    __syncthreads();
    // inclusive Hillis-Steele scan
    for (int st = 1; st < 256; st <<= 1) {
        int add = (o >= st) ? scan[o - st] : 0;
        __syncthreads();
        scan[o] += add;
        __syncthreads();
    }
    int nact = scan[255];
    int slot = m ? (scan[o] - 1) : (nact + (o - scan[o]));
    g_slot[o] = slot;
    g_perm[slot] = o;
    if (o == 0) g_nact = nact;
}

// ---------------- 5b: weight prep (fp32 -> compacted, permuted fp16) --------
__global__ void wprep_kernel(const float* __restrict__ w) {
    int i = blockIdx.x * blockDim.x + threadIdx.x;
    if (i >= OCH * KW2) return;
    int o = i / KW2, rem = i % KW2;
    int c = rem / 9, t = rem % 9;          // k = c*9 + t
    float v = w[i];
    int s = g_slot[o];
    char* base = (char*)g_wq;
    *(__half*)(base + ((size_t)t * 256 + s) * 128 + cslot(c)) = __float2half(v);
}

// ---------------- 5c: zero-fill inactive output planes ----------------------
__global__ void zerofill_kernel(float* __restrict__ out) {
    int oc = blockIdx.x, img = blockIdx.y;
    if (g_mask[oc]) return;
    float4 z = {0.f, 0.f, 0.f, 0.f};
    float4* p = (float4*)(out + (((size_t)img * OCH + oc) << 14));
    for (int i = threadIdx.x; i < 4096; i += 256) p[i] = z;
}

// ---------------- 6: sparse warp-MMA implicit-GEMM conv ---------------------
// CTA: M=32 active slots (group bx), N=512 px (4 rows), K=576.
// 16 warps, warp tile 32x32 (mt=2, nt=4). fp16 MMA, pitch 160 (conflict-free).
#define PITCH   160
#define T_OFF   512
#define T_PER   124800        // 6*130*160
#define A_OFF   125312        // 512 + T_PER
#define A_BUF   5120          // 32*160
#define SMEM_CONV 135552      // A_OFF + 2*A_BUF

__device__ __forceinline__ void copyA_tap(uint32_t sb, int t, int buf, int sg, int tid) {
    if (tid < 256) {
        const char* gb = (const char*)g_wq;
        int row = tid >> 3, j = tid & 7;
        const char* src = gb + ((size_t)t * 256 + sg + row) * 128 + j * 16;
        uint32_t dst = sb + A_OFF + buf * A_BUF + row * PITCH + j * 16;
        cp_async16(dst, src);
    }
}

__global__ void __launch_bounds__(512, 1)
conv_mma_kernel(const float* __restrict__ x, float* __restrict__ out) {
    int sg = blockIdx.x * 32;            // slot-group base
    if (sg >= g_nact) return;            // uniform across CTA

    extern __shared__ __align__(16) char smem[];
    uint32_t sb = smem_u32(smem);
    int tid = threadIdx.x, wid = tid >> 5, lane = tid & 31;
    int rp = blockIdx.y, img = blockIdx.z;
    int y0 = rp * 4;

    float* smask = (float*)smem;         // [32]
    int*   sperm = (int*)(smem + 128);   // [32]
    if (tid < 32) {
        int gs = sg + tid;
        sperm[tid] = g_perm[gs];
        smask[tid] = (gs < g_nact) ? 1.f : 0.f;
    }

    // prefetch A tap 0
    copyA_tap(sb, 0, 0, sg, tid);
    CP_COMMIT();

    // zero T slab
    {
        uint4 z = {0, 0, 0, 0};
        uint4* tz = (uint4*)(smem + T_OFF);
        for (int e = tid; e < T_PER / 16; e += 512) tz[e] = z;
    }
    __syncthreads();

    // build T: rows y0-1 .. y0+4, fp16, channel-permuted 128B rows, pitch 160
    for (int e = tid; e < 6 * C_IN * HW; e += 512) {
        int rr = e >> 13, rem = e & 8191;
        int c = rem >> 7, xc = rem & 127;
        int y = y0 - 1 + rr;
        if (y >= 0 && y < HW) {
            float v = x[((img * C_IN + c) * HW + y) * HW + xc];
            int off = (rr * 130 + xc + 1) * PITCH + cslot(c);
            *(__half*)(smem + T_OFF + off) = __float2half(v);
        }
    }
    __syncthreads();

    int n0w  = wid * 32;
    int yrel = n0w >> 7;         // 0..3
    int x0w  = n0w & 127;        // 0,32,64,96
    int lr   = lane >> 2;        // 0..7
    int lj   = lane & 3;         // 0..3

    float acc[2][4][4];
    #pragma unroll
    for (int mt = 0; mt < 2; mt++)
        #pragma unroll
        for (int nt = 0; nt < 4; nt++)
            #pragma unroll
            for (int q = 0; q < 4; q++) acc[mt][nt][q] = 0.f;

    for (int t = 0; t < 9; t++) {
        int kh = t / 3, kw = t % 3, buf = t & 1;
        CP_WAIT0();
        __syncthreads();
        if (t < 8) { copyA_tap(sb, t + 1, buf ^ 1, sg, tid); CP_COMMIT(); }

        const char* Ah = smem + A_OFF + buf * A_BUF;
        const char* Tb = smem + T_OFF + ((yrel + kh) * 130 + kw) * PITCH;

        #pragma unroll
        for (int ks = 0; ks < 4; ks++) {
            int fo = ks * 32 + lj * 8;
            uint32_t ah[2][4];
            #pragma unroll
            for (int mt = 0; mt < 2; mt++) {
                int r0 = (mt * 16 + lr) * PITCH + fo;
                int r8 = r0 + 8 * PITCH;
                uint2 w0 = *(const uint2*)(Ah + r0);
                uint2 w8 = *(const uint2*)(Ah + r8);
                ah[mt][0] = w0.x; ah[mt][2] = w0.y;
                ah[mt][1] = w8.x; ah[mt][3] = w8.y;
            }
            #pragma unroll
            for (int nt = 0; nt < 4; nt++) {
                int xo = (x0w + nt * 8 + lr) * PITCH + fo;
                uint2 bv = *(const uint2*)(Tb + xo);
                mma16816(acc[0][nt], ah[0][0], ah[0][1], ah[0][2], ah[0][3], bv.x, bv.y);
                mma16816(acc[1][nt], ah[1][0], ah[1][1], ah[1][2], ah[1][3], bv.x, bv.y);
            }
        }
    }

    // epilogue: scatter to active output channels (masked exact zeros past nact)
    int y = y0 + yrel;
    #pragma unroll
    for (int mt = 0; mt < 2; mt++) {
        int s0 = mt * 16 + lr;
        float mk0 = smask[s0];
        float mk1 = smask[s0 + 8];
        size_t b0 = (((size_t)img * OCH + sperm[s0]) * HW + y) * HW;
        size_t b1 = (((size_t)img * OCH + sperm[s0 + 8]) * HW + y) * HW;
        #pragma unroll
        for (int nt = 0; nt < 4; nt++) {
            int xcol = x0w + nt * 8 + lj * 2;
            float2 v0 = { acc[mt][nt][0] * mk0, acc[mt][nt][1] * mk0 };
            float2 v1 = { acc[mt][nt][2] * mk1, acc[mt][nt][3] * mk1 };
            *(float2*)(out + b0 + xcol) = v0;
            *(float2*)(out + b1 + xcol) = v1;
        }
    }
}

// ---------------- launch ----------------
extern "C" void kernel_launch(void* const* d_in, const int* in_sizes, int n_in,
                              void* d_out, int out_size) {
    const float* x = (const float*)d_in[0];   // [32,64,128,128]
    const float* w = (const float*)d_in[1];   // [256,64,3,3]
    const float* a = (const float*)d_in[2];   // [8,67,3,3]
    const float* b = (const float*)d_in[3];   // [8]
    float* out = (float*)d_out;               // [32,256,128,128]

    cudaFuncSetAttribute(conv_mma_kernel,
                         cudaFuncAttributeMaxDynamicSharedMemorySize, SMEM_CONV);

    zero_hist_kernel<<<16, 256>>>();
    norms_kernel<<<1, 256>>>(w);
    kbuckets_kernel<<<256, 256>>>(w, a, b);
    vote_kernel<<<dim3(8, 8, NB), 256>>>(x, a, b);
    argmax_kernel<<<1, 256>>>();
    maskcompact_kernel<<<1, 256>>>();
    wprep_kernel<<<576, 256>>>(w);
    zerofill_kernel<<<dim3(OCH, NB), 256>>>(out);
    conv_mma_kernel<<<dim3(8, 32, NB), 512, SMEM_CONV>>>(x, out);
}

// round 9
// speedup vs baseline: 1.7096x; 1.7096x over previous
#include <cuda_runtime.h>
#include <cuda_fp16.h>
#include <math.h>
#include <stdint.h>

// ---------------- problem constants ----------------
#define NB     32
#define C_IN   64
#define HW     128
#define OCH    256
#define HASH   8
#define D_A    603
#define KW2    576
#define MPOW   27
#define TSZ    512
#define RADIUS 4.0f
#define UBND   0.99f

// ---------------- device scratch ----------------
__device__ int   g_hist[HASH * TSZ];
__device__ float g_norm[OCH];
__device__ float g_scale;
__device__ int   g_kbuckets[HASH * OCH];
__device__ int   g_voted[HASH];
__device__ int   g_mask[OCH];
// permuted fp16 weights: [tap 9][oc 256][128 B]
__device__ uint4 g_wq[18432];            // 294,912 B
// pre-converted fp16 input: [img][y][xc] -> 128B channel-permuted row
__device__ uint4 g_xh[NB * HW * HW * 8]; // 64 MB

// ---------------- helpers ----------------
__device__ __forceinline__ uint32_t smem_u32(const void* p) {
    uint32_t a;
    asm("{ .reg .u64 t; cvta.to.shared.u64 t, %1; cvt.u32.u64 %0, t; }" : "=r"(a) : "l"(p));
    return a;
}
// channel -> byte offset inside a 128B packed row (pair-permuted for mma frags)
__device__ __forceinline__ int cslot(int c) {
    int gg = c >> 4, r = c & 15, q = r >> 1, odd = r & 1;
    int slot = (q < 4) ? (q << 1) : (((q - 4) << 1) | 1);
    return gg * 32 + slot * 4 + odd * 2;
}
__device__ __forceinline__ void mma16816(float* c, uint32_t a0, uint32_t a1,
                                         uint32_t a2, uint32_t a3,
                                         uint32_t b0, uint32_t b1) {
    asm volatile(
        "mma.sync.aligned.m16n8k16.row.col.f32.f16.f16.f32 "
        "{%0,%1,%2,%3}, {%4,%5,%6,%7}, {%8,%9}, {%0,%1,%2,%3};"
        : "+f"(c[0]), "+f"(c[1]), "+f"(c[2]), "+f"(c[3])
        : "r"(a0), "r"(a1), "r"(a2), "r"(a3), "r"(b0), "r"(b1));
}
__device__ __forceinline__ void cp_async16(uint32_t dst, const void* src) {
    asm volatile("{ .reg .u64 gp; cvta.to.global.u64 gp, %1; "
                 "cp.async.cg.shared.global [%0], [gp], 16; }"
                 :: "r"(dst), "l"(src) : "memory");
}
#define CP_COMMIT() asm volatile("cp.async.commit_group;" ::: "memory")
#define CP_WAIT0()  asm volatile("cp.async.wait_group 0;" ::: "memory")

// ---------------- 0: zero hist ----------------
__global__ void zero_hist_kernel() {
    int i = blockIdx.x * blockDim.x + threadIdx.x;
    if (i < HASH * TSZ) g_hist[i] = 0;
}

// ---------------- 1: norms + scale ----------------
__global__ void norms_kernel(const float* __restrict__ w) {
    __shared__ float sn[256];
    int o = threadIdx.x;
    const float* row = w + o * KW2;
    float s = 0.f;
    for (int j = 0; j < KW2; j++) { float v = row[j]; s += v * v; }
    float nrm = sqrtf(s);
    g_norm[o] = nrm;
    sn[o] = nrm;
    __syncthreads();
    for (int st = 128; st > 0; st >>= 1) {
        if (o < st) sn[o] = fmaxf(sn[o], sn[o + st]);
        __syncthreads();
    }
    if (o == 0) g_scale = UBND / sn[0];
}

// ---------------- 2: kernel buckets ----------------
__global__ void kbuckets_kernel(const float* __restrict__ w,
                                const float* __restrict__ a,
                                const float* __restrict__ b) {
    int wid  = (blockIdx.x * blockDim.x + threadIdx.x) >> 5;
    int lane = threadIdx.x & 31;
    if (wid >= HASH * OCH) return;
    int h = wid >> 8, o = wid & 255;
    const float* ar = a + h * D_A;
    const float* wr = w + o * KW2;
    float s = 0.f;
    for (int j = lane; j < KW2; j += 32) s += ar[j] * wr[j];
    #pragma unroll
    for (int off = 16; off; off >>= 1) s += __shfl_down_sync(0xffffffffu, s, off);
    if (lane == 0) {
        float dot = g_scale * s;
        float t = g_scale * g_norm[o];
        #pragma unroll 1
        for (int p = 0; p < MPOW; p++) { t = t * t; dot += ar[KW2 + p] * t; }
        float v = floorf((dot + b[h]) / RADIUS);
        g_kbuckets[h * OCH + o] = (int)fabsf(fmodf(v, (float)TSZ));
    }
}

// ---------------- 2b: weight prep (fp32 -> permuted fp16) -------------------
__global__ void wprep_kernel(const float* __restrict__ w) {
    int i = blockIdx.x * blockDim.x + threadIdx.x;
    if (i >= OCH * KW2) return;
    int o = i / KW2, rem = i % KW2;
    int c = rem / 9, t = rem % 9;
    char* base = (char*)g_wq;
    *(__half*)(base + ((size_t)t * 256 + o) * 128 + cslot(c)) = __float2half(w[i]);
}

// ---------------- 2c: input prep (fp32 -> permuted fp16 rows) ---------------
// block = (y, img); staging uses a 16B XOR swizzle so both phases avoid
// 32-way conflicts.
__global__ void xprep_kernel(const float* __restrict__ x) {
    __shared__ char st[128 * 128];    // 16 KB: [xc][128B permuted row]
    int y = blockIdx.x, img = blockIdx.y;
    int tid = threadIdx.x;
    for (int e = tid; e < C_IN * HW; e += 256) {
        int c = e >> 7, xc = e & 127;               // consecutive tid -> xc
        float v = x[((img * C_IN + c) * HW + y) * HW + xc];
        int off = xc * 128 + (cslot(c) ^ ((xc & 7) << 4));
        *(__half*)(st + off) = __float2half(v);
    }
    __syncthreads();
    uint4* dst = g_xh + ((size_t)(img * HW + y) * HW) * 8;
    for (int e = tid; e < 128 * 8; e += 256) {
        int xc = e >> 3, j = e & 7;
        dst[e] = *(const uint4*)(st + xc * 128 + ((j ^ (xc & 7)) << 4));
    }
}

// ---------------- 3: vote (32x16 tiles, 2 px/thread) ------------------------
__global__ void vote_kernel(const float* __restrict__ x,
                            const float* __restrict__ a,
                            const float* __restrict__ b) {
    __shared__ float xs[4][18][36];
    __shared__ float ws[4][9][HASH];
    __shared__ float sb[HASH];
    __shared__ int   shist[HASH * TSZ];

    int tid = threadIdx.x;
    int n = blockIdx.z, x0 = blockIdx.x * 32, y0 = blockIdx.y * 16;

    for (int e = tid; e < HASH * TSZ; e += 256) shist[e] = 0;
    if (tid < HASH) sb[tid] = b[tid];

    int col = tid & 31, py = (tid >> 5) << 1;
    float acc[HASH][2];
    #pragma unroll
    for (int h = 0; h < HASH; h++) { acc[h][0] = 0.f; acc[h][1] = 0.f; }

    for (int c0 = 0; c0 < 68; c0 += 4) {
        __syncthreads();
        for (int e = tid; e < 4 * 18 * 34; e += 256) {
            int c = e / 612, rem = e % 612;
            int ry = rem / 34, rx = rem % 34;
            int cg = c0 + c;
            int gy = y0 - 1 + ry, gx = x0 - 1 + rx;
            float v = 0.f;
            if (cg < 67 && gy >= 0 && gy < HW && gx >= 0 && gx < HW)
                v = (cg < C_IN) ? x[((n * C_IN + cg) * HW + gy) * HW + gx] : 0.5f;
            xs[c][ry][rx] = v;
        }
        for (int e = tid; e < 4 * 9 * HASH; e += 256) {
            int h = e % HASH, rem = e / HASH;
            int c = rem / 9, khw = rem % 9;
            int cg = c0 + c;
            ws[c][khw][h] = (cg < 67) ? a[h * D_A + cg * 9 + khw] : 0.f;
        }
        __syncthreads();
        #pragma unroll
        for (int c = 0; c < 4; c++)
            #pragma unroll
            for (int kh = 0; kh < 3; kh++)
                #pragma unroll
                for (int kw = 0; kw < 3; kw++) {
                    float xv0 = xs[c][py + kh][col + kw];
                    float xv1 = xs[c][py + 1 + kh][col + kw];
                    #pragma unroll
                    for (int h = 0; h < HASH; h++) {
                        float wv = ws[c][kh * 3 + kw][h];
                        acc[h][0] += wv * xv0;
                        acc[h][1] += wv * xv1;
                    }
                }
    }
    __syncthreads();
    #pragma unroll
    for (int h = 0; h < HASH; h++) {
        #pragma unroll
        for (int p = 0; p < 2; p++) {
            float v = floorf((acc[h][p] + sb[h]) / RADIUS);
            int bk = (int)fabsf(fmodf(v, (float)TSZ));
            atomicAdd(&shist[h * TSZ + bk], 1);
        }
    }
    __syncthreads();
    for (int e = tid; e < HASH * TSZ; e += 256) {
        int v = shist[e];
        if (v) atomicAdd(&g_hist[e], v);
    }
}

// ---------------- 4: argmax ----------------
__global__ void argmax_kernel() {
    int w = threadIdx.x >> 5, lane = threadIdx.x & 31;
    int best = -1, bidx = 0;
    for (int j = lane; j < TSZ; j += 32) {
        int c = g_hist[w * TSZ + j];
        if (c > best) { best = c; bidx = j; }
    }
    #pragma unroll
    for (int off = 16; off; off >>= 1) {
        int ob = __shfl_down_sync(0xffffffffu, best, off);
        int oi = __shfl_down_sync(0xffffffffu, bidx, off);
        if (ob > best || (ob == best && oi < bidx)) { best = ob; bidx = oi; }
    }
    if (lane == 0) g_voted[w] = bidx;
}

// ---------------- 5: mask ----------------
__global__ void mask_kernel() {
    __shared__ int sv[HASH];
    if (threadIdx.x < HASH) sv[threadIdx.x] = g_voted[threadIdx.x];
    __syncthreads();
    int o = threadIdx.x, m = 0;
    #pragma unroll
    for (int h = 0; h < HASH; h++) {
        int kb = g_kbuckets[h * OCH + o];
        #pragma unroll
        for (int j = 0; j < HASH; j++) m |= (kb == sv[j]);
    }
    g_mask[o] = m;
}

// ---------------- 6: dense warp-MMA implicit-GEMM conv ----------------------
// CTA 512 thr: M=128 oc (ocg half), N=256 px (2 rows), K=576.
// Warp grid 4(M)x4(N); warp tile 32x64. fp16 MMA, pitch 160 (conflict-free).
// T-slab copied from pre-converted g_xh via cp.async (no per-CTA conversion).
#define PITCH   160
#define T_OFF   512
#define T_PER   83200         // 4*130*160
#define A_OFF   83712         // 512 + T_PER
#define A_BUF   20480         // 128*160
#define SMEM_CONV 124672      // A_OFF + 2*A_BUF

__device__ __forceinline__ void copyA_tap(uint32_t sb, int t, int buf, int ocg, int tid) {
    const char* gb = (const char*)g_wq;
    #pragma unroll
    for (int q = 0; q < 2; q++) {
        int e = q * 512 + tid;
        int oc = e >> 3, j = e & 7;
        const char* src = gb + ((size_t)t * 256 + ocg * 128 + oc) * 128 + j * 16;
        uint32_t dst = sb + A_OFF + buf * A_BUF + oc * PITCH + j * 16;
        cp_async16(dst, src);
    }
}

__global__ void __launch_bounds__(512, 1)
conv_mma_kernel(float* __restrict__ out) {
    extern __shared__ __align__(16) char smem[];
    uint32_t sb = smem_u32(smem);
    int tid = threadIdx.x, wid = tid >> 5, lane = tid & 31;
    int ocg = blockIdx.x, rp = blockIdx.y, img = blockIdx.z;
    int y0 = rp * 2;

    float* smask = (float*)smem;
    if (tid < 128) smask[tid] = g_mask[ocg * 128 + tid] ? 1.f : 0.f;

    // T slab: edge columns + OOB rows zeroed, interior via cp.async
    uint4 z = {0, 0, 0, 0};
    if (tid < 64) {
        int rr = tid >> 4, ec = (tid >> 3) & 1, j = tid & 7;
        int xi = ec ? 129 : 0;
        *(uint4*)(smem + T_OFF + (rr * 130 + xi) * PITCH + j * 16) = z;
    }
    for (int e = tid; e < 4 * 128 * 8; e += 512) {
        int rr = e >> 10, rem = e & 1023, xc = rem >> 3, j = rem & 7;
        int y = y0 - 1 + rr;
        uint32_t doff = (uint32_t)((rr * 130 + xc + 1) * PITCH + j * 16);
        if (y >= 0 && y < HW)
            cp_async16(sb + T_OFF + doff,
                       (const char*)g_xh + (((size_t)img * HW + y) * HW + xc) * 128 + j * 16);
        else
            *(uint4*)(smem + T_OFF + doff) = z;
    }
    // prefetch A tap 0 (same cp.async group as T)
    copyA_tap(sb, 0, 0, ocg, tid);
    CP_COMMIT();

    int m0   = (wid & 3) * 32;
    int n0w  = (wid >> 2) * 64;
    int yrel = n0w >> 7;
    int x0w  = n0w & 127;
    int lr   = lane >> 2;
    int lj   = lane & 3;

    float acc[2][8][4];
    #pragma unroll
    for (int mt = 0; mt < 2; mt++)
        #pragma unroll
        for (int nt = 0; nt < 8; nt++)
            #pragma unroll
            for (int q = 0; q < 4; q++) acc[mt][nt][q] = 0.f;

    for (int t = 0; t < 9; t++) {
        int kh = t / 3, kw = t % 3, buf = t & 1;
        CP_WAIT0();
        __syncthreads();
        if (t < 8) { copyA_tap(sb, t + 1, buf ^ 1, ocg, tid); CP_COMMIT(); }

        const char* Ah = smem + A_OFF + buf * A_BUF;
        const char* Tb = smem + T_OFF + ((yrel + kh) * 130 + kw) * PITCH;

        #pragma unroll
        for (int ks = 0; ks < 4; ks++) {
            int fo = ks * 32 + lj * 8;
            uint32_t ah[2][4];
            #pragma unroll
            for (int mt = 0; mt < 2; mt++) {
                int r0 = (m0 + mt * 16 + lr) * PITCH + fo;
                int r8 = r0 + 8 * PITCH;
                uint2 w0 = *(const uint2*)(Ah + r0);
                uint2 w8 = *(const uint2*)(Ah + r8);
                ah[mt][0] = w0.x; ah[mt][2] = w0.y;
                ah[mt][1] = w8.x; ah[mt][3] = w8.y;
            }
            #pragma unroll
            for (int nt = 0; nt < 8; nt++) {
                int xo = (x0w + nt * 8 + lr) * PITCH + fo;
                uint2 bv = *(const uint2*)(Tb + xo);
                mma16816(acc[0][nt], ah[0][0], ah[0][1], ah[0][2], ah[0][3], bv.x, bv.y);
                mma16816(acc[1][nt], ah[1][0], ah[1][1], ah[1][2], ah[1][3], bv.x, bv.y);
            }
        }
    }

    // epilogue: masked stores
    int y = y0 + yrel;
    #pragma unroll
    for (int mt = 0; mt < 2; mt++) {
        int mrow = m0 + mt * 16 + lr;
        float mk0 = smask[mrow];
        float mk1 = smask[mrow + 8];
        int oc0 = ocg * 128 + mrow;
        size_t b0 = ((size_t)(img * OCH + oc0) * HW + y) * HW;
        size_t b1 = b0 + (size_t)8 * HW * HW;
        #pragma unroll
        for (int nt = 0; nt < 8; nt++) {
            int xcol = x0w + nt * 8 + lj * 2;
            float2 v0 = { acc[mt][nt][0] * mk0, acc[mt][nt][1] * mk0 };
            float2 v1 = { acc[mt][nt][2] * mk1, acc[mt][nt][3] * mk1 };
            *(float2*)(out + b0 + xcol) = v0;
            *(float2*)(out + b1 + xcol) = v1;
        }
    }
}

// ---------------- launch ----------------
extern "C" void kernel_launch(void* const* d_in, const int* in_sizes, int n_in,
                              void* d_out, int out_size) {
    const float* x = (const float*)d_in[0];   // [32,64,128,128]
    const float* w = (const float*)d_in[1];   // [256,64,3,3]
    const float* a = (const float*)d_in[2];   // [8,67,3,3]
    const float* b = (const float*)d_in[3];   // [8]
    float* out = (float*)d_out;               // [32,256,128,128]

    cudaFuncSetAttribute(conv_mma_kernel,
                         cudaFuncAttributeMaxDynamicSharedMemorySize, SMEM_CONV);

    zero_hist_kernel<<<16, 256>>>();
    norms_kernel<<<1, 256>>>(w);
    kbuckets_kernel<<<256, 256>>>(w, a, b);
    wprep_kernel<<<576, 256>>>(w);
    xprep_kernel<<<dim3(HW, NB), 256>>>(x);
    vote_kernel<<<dim3(4, 8, NB), 256>>>(x, a, b);
    argmax_kernel<<<1, 256>>>();
    mask_kernel<<<1, 256>>>();
    conv_mma_kernel<<<dim3(2, 64, NB), 512, SMEM_CONV>>>(out);
}

// round 10
// speedup vs baseline: 1.7687x; 1.0346x over previous
#include <cuda_runtime.h>
#include <cuda_fp16.h>
#include <math.h>
#include <stdint.h>

// ---------------- problem constants ----------------
#define NB     32
#define C_IN   64
#define HW     128
#define OCH    256
#define HASH   8
#define D_A    603
#define KW2    576
#define MPOW   27
#define TSZ    512
#define RADIUS 4.0f
#define UBND   0.99f

// ---------------- device scratch ----------------
__device__ int   g_hist[HASH * TSZ];
__device__ float g_norm[OCH];
__device__ float g_scale;
__device__ int   g_kbuckets[HASH * OCH];
__device__ int   g_voted[HASH];
__device__ int   g_mask[OCH];
// permuted fp16 weights: [tap 9][oc 256][128 B]
__device__ uint4 g_wq[18432];            // 294,912 B
// pre-converted fp16 input: [img][y][xc] -> 128B channel-permuted row
__device__ uint4 g_xh[NB * HW * HW * 8]; // 64 MB

// ---------------- helpers ----------------
__device__ __forceinline__ uint32_t smem_u32(const void* p) {
    uint32_t a;
    asm("{ .reg .u64 t; cvta.to.shared.u64 t, %1; cvt.u32.u64 %0, t; }" : "=r"(a) : "l"(p));
    return a;
}
// channel -> byte offset inside a 128B packed row (pair-permuted for mma frags)
__device__ __forceinline__ int cslot(int c) {
    int gg = c >> 4, r = c & 15, q = r >> 1, odd = r & 1;
    int slot = (q < 4) ? (q << 1) : (((q - 4) << 1) | 1);
    return gg * 32 + slot * 4 + odd * 2;
}
__device__ __forceinline__ void mma16816(float* c, uint32_t a0, uint32_t a1,
                                         uint32_t a2, uint32_t a3,
                                         uint32_t b0, uint32_t b1) {
    asm volatile(
        "mma.sync.aligned.m16n8k16.row.col.f32.f16.f16.f32 "
        "{%0,%1,%2,%3}, {%4,%5,%6,%7}, {%8,%9}, {%0,%1,%2,%3};"
        : "+f"(c[0]), "+f"(c[1]), "+f"(c[2]), "+f"(c[3])
        : "r"(a0), "r"(a1), "r"(a2), "r"(a3), "r"(b0), "r"(b1));
}
__device__ __forceinline__ void cp_async16(uint32_t dst, const void* src) {
    asm volatile("{ .reg .u64 gp; cvta.to.global.u64 gp, %1; "
                 "cp.async.cg.shared.global [%0], [gp], 16; }"
                 :: "r"(dst), "l"(src) : "memory");
}
#define CP_COMMIT() asm volatile("cp.async.commit_group;" ::: "memory")
#define CP_WAIT0()  asm volatile("cp.async.wait_group 0;" ::: "memory")

// ---------------- 0: zero hist ----------------
__global__ void zero_hist_kernel() {
    int i = blockIdx.x * blockDim.x + threadIdx.x;
    if (i < HASH * TSZ) g_hist[i] = 0;
}

// ---------------- 1: norms + scale ----------------
__global__ void norms_kernel(const float* __restrict__ w) {
    __shared__ float sn[256];
    int o = threadIdx.x;
    const float* row = w + o * KW2;
    float s = 0.f;
    for (int j = 0; j < KW2; j++) { float v = row[j]; s += v * v; }
    float nrm = sqrtf(s);
    g_norm[o] = nrm;
    sn[o] = nrm;
    __syncthreads();
    for (int st = 128; st > 0; st >>= 1) {
        if (o < st) sn[o] = fmaxf(sn[o], sn[o + st]);
        __syncthreads();
    }
    if (o == 0) g_scale = UBND / sn[0];
}

// ---------------- 2: kernel buckets ----------------
__global__ void kbuckets_kernel(const float* __restrict__ w,
                                const float* __restrict__ a,
                                const float* __restrict__ b) {
    int wid  = (blockIdx.x * blockDim.x + threadIdx.x) >> 5;
    int lane = threadIdx.x & 31;
    if (wid >= HASH * OCH) return;
    int h = wid >> 8, o = wid & 255;
    const float* ar = a + h * D_A;
    const float* wr = w + o * KW2;
    float s = 0.f;
    for (int j = lane; j < KW2; j += 32) s += ar[j] * wr[j];
    #pragma unroll
    for (int off = 16; off; off >>= 1) s += __shfl_down_sync(0xffffffffu, s, off);
    if (lane == 0) {
        float dot = g_scale * s;
        float t = g_scale * g_norm[o];
        #pragma unroll 1
        for (int p = 0; p < MPOW; p++) { t = t * t; dot += ar[KW2 + p] * t; }
        float v = floorf((dot + b[h]) / RADIUS);
        g_kbuckets[h * OCH + o] = (int)fabsf(fmodf(v, (float)TSZ));
    }
}

// ---------------- 2b: weight prep (fp32 -> permuted fp16) -------------------
__global__ void wprep_kernel(const float* __restrict__ w) {
    int i = blockIdx.x * blockDim.x + threadIdx.x;
    if (i >= OCH * KW2) return;
    int o = i / KW2, rem = i % KW2;
    int c = rem / 9, t = rem % 9;
    char* base = (char*)g_wq;
    *(__half*)(base + ((size_t)t * 256 + o) * 128 + cslot(c)) = __float2half(w[i]);
}

// ---------------- 2c: input prep (fp32 -> permuted fp16 rows) ---------------
__global__ void xprep_kernel(const float* __restrict__ x) {
    __shared__ char st[128 * 128];    // 16 KB: [xc][128B permuted row]
    int y = blockIdx.x, img = blockIdx.y;
    int tid = threadIdx.x;
    for (int e = tid; e < C_IN * HW; e += 256) {
        int c = e >> 7, xc = e & 127;
        float v = x[((img * C_IN + c) * HW + y) * HW + xc];
        int off = xc * 128 + (cslot(c) ^ ((xc & 7) << 4));
        *(__half*)(st + off) = __float2half(v);
    }
    __syncthreads();
    uint4* dst = g_xh + ((size_t)(img * HW + y) * HW) * 8;
    for (int e = tid; e < 128 * 8; e += 256) {
        int xc = e >> 3, j = e & 7;
        dst[e] = *(const uint4*)(st + xc * 128 + ((j ^ (xc & 7)) << 4));
    }
}

// ---------------- 3: vote (32x16 tiles, 2 px/thread) ------------------------
__global__ void vote_kernel(const float* __restrict__ x,
                            const float* __restrict__ a,
                            const float* __restrict__ b) {
    __shared__ float xs[4][18][36];
    __shared__ float ws[4][9][HASH];
    __shared__ float sb[HASH];
    __shared__ int   shist[HASH * TSZ];

    int tid = threadIdx.x;
    int n = blockIdx.z, x0 = blockIdx.x * 32, y0 = blockIdx.y * 16;

    for (int e = tid; e < HASH * TSZ; e += 256) shist[e] = 0;
    if (tid < HASH) sb[tid] = b[tid];

    int col = tid & 31, py = (tid >> 5) << 1;
    float acc[HASH][2];
    #pragma unroll
    for (int h = 0; h < HASH; h++) { acc[h][0] = 0.f; acc[h][1] = 0.f; }

    for (int c0 = 0; c0 < 68; c0 += 4) {
        __syncthreads();
        for (int e = tid; e < 4 * 18 * 34; e += 256) {
            int c = e / 612, rem = e % 612;
            int ry = rem / 34, rx = rem % 34;
            int cg = c0 + c;
            int gy = y0 - 1 + ry, gx = x0 - 1 + rx;
            float v = 0.f;
            if (cg < 67 && gy >= 0 && gy < HW && gx >= 0 && gx < HW)
                v = (cg < C_IN) ? x[((n * C_IN + cg) * HW + gy) * HW + gx] : 0.5f;
            xs[c][ry][rx] = v;
        }
        for (int e = tid; e < 4 * 9 * HASH; e += 256) {
            int h = e % HASH, rem = e / HASH;
            int c = rem / 9, khw = rem % 9;
            int cg = c0 + c;
            ws[c][khw][h] = (cg < 67) ? a[h * D_A + cg * 9 + khw] : 0.f;
        }
        __syncthreads();
        #pragma unroll
        for (int c = 0; c < 4; c++)
            #pragma unroll
            for (int kh = 0; kh < 3; kh++)
                #pragma unroll
                for (int kw = 0; kw < 3; kw++) {
                    float xv0 = xs[c][py + kh][col + kw];
                    float xv1 = xs[c][py + 1 + kh][col + kw];
                    #pragma unroll
                    for (int h = 0; h < HASH; h++) {
                        float wv = ws[c][kh * 3 + kw][h];
                        acc[h][0] += wv * xv0;
                        acc[h][1] += wv * xv1;
                    }
                }
    }
    __syncthreads();
    #pragma unroll
    for (int h = 0; h < HASH; h++) {
        #pragma unroll
        for (int p = 0; p < 2; p++) {
            float v = floorf((acc[h][p] + sb[h]) / RADIUS);
            int bk = (int)fabsf(fmodf(v, (float)TSZ));
            atomicAdd(&shist[h * TSZ + bk], 1);
        }
    }
    __syncthreads();
    for (int e = tid; e < HASH * TSZ; e += 256) {
        int v = shist[e];
        if (v) atomicAdd(&g_hist[e], v);
    }
}

// ---------------- 4: argmax ----------------
__global__ void argmax_kernel() {
    int w = threadIdx.x >> 5, lane = threadIdx.x & 31;
    int best = -1, bidx = 0;
    for (int j = lane; j < TSZ; j += 32) {
        int c = g_hist[w * TSZ + j];
        if (c > best) { best = c; bidx = j; }
    }
    #pragma unroll
    for (int off = 16; off; off >>= 1) {
        int ob = __shfl_down_sync(0xffffffffu, best, off);
        int oi = __shfl_down_sync(0xffffffffu, bidx, off);
        if (ob > best || (ob == best && oi < bidx)) { best = ob; bidx = oi; }
    }
    if (lane == 0) g_voted[w] = bidx;
}

// ---------------- 5: mask ----------------
__global__ void mask_kernel() {
    __shared__ int sv[HASH];
    if (threadIdx.x < HASH) sv[threadIdx.x] = g_voted[threadIdx.x];
    __syncthreads();
    int o = threadIdx.x, m = 0;
    #pragma unroll
    for (int h = 0; h < HASH; h++) {
        int kb = g_kbuckets[h * OCH + o];
        #pragma unroll
        for (int j = 0; j < HASH; j++) m |= (kb == sv[j]);
    }
    g_mask[o] = m;
}

// ---------------- 6: dense warp-MMA implicit-GEMM conv ----------------------
// CTA 512 thr: M=128 oc (ocg half), N=256 px (2 rows), K=576.
// Warp grid 4(M)x4(N); warp tile 32x64. fp16 MMA, pitch 160 (conflict-free).
// 3 kh-stages; A staged 3 taps at a time; inner (kw,ks) loop barrier-free.
#define PITCH   160
#define T_OFF   512
#define T_PER   83200         // 4*130*160
#define A_OFF   83712         // 512 + T_PER
#define A_TAP   20480         // 128*160
#define A_STG   61440         // 3 taps
#define SMEM_CONV 206592      // A_OFF + 2*A_STG

__device__ __forceinline__ void copyA_stage(uint32_t sb, int kst, int buf, int ocg, int tid) {
    const char* gb = (const char*)g_wq;
    #pragma unroll
    for (int q = 0; q < 6; q++) {
        int e = q * 512 + tid;            // 0..3071
        int tapi = e >> 10;               // 0..2
        int idx  = e & 1023;
        int oc = idx >> 3, j = idx & 7;
        int t = kst * 3 + tapi;
        const char* src = gb + ((size_t)t * 256 + ocg * 128 + oc) * 128 + j * 16;
        uint32_t dst = sb + A_OFF + buf * A_STG + tapi * A_TAP + oc * PITCH + j * 16;
        cp_async16(dst, src);
    }
}

__global__ void __launch_bounds__(512, 1)
conv_mma_kernel(float* __restrict__ out) {
    extern __shared__ __align__(16) char smem[];
    uint32_t sb = smem_u32(smem);
    int tid = threadIdx.x, wid = tid >> 5, lane = tid & 31;
    int ocg = blockIdx.x, rp = blockIdx.y, img = blockIdx.z;
    int y0 = rp * 2;

    float* smask = (float*)smem;
    if (tid < 128) smask[tid] = g_mask[ocg * 128 + tid] ? 1.f : 0.f;

    // T slab: edge columns + OOB rows zeroed, interior via cp.async
    uint4 z = {0, 0, 0, 0};
    if (tid < 64) {
        int rr = tid >> 4, ec = (tid >> 3) & 1, j = tid & 7;
        int xi = ec ? 129 : 0;
        *(uint4*)(smem + T_OFF + (rr * 130 + xi) * PITCH + j * 16) = z;
    }
    for (int e = tid; e < 4 * 128 * 8; e += 512) {
        int rr = e >> 10, rem = e & 1023, xc = rem >> 3, j = rem & 7;
        int y = y0 - 1 + rr;
        uint32_t doff = (uint32_t)((rr * 130 + xc + 1) * PITCH + j * 16);
        if (y >= 0 && y < HW)
            cp_async16(sb + T_OFF + doff,
                       (const char*)g_xh + (((size_t)img * HW + y) * HW + xc) * 128 + j * 16);
        else
            *(uint4*)(smem + T_OFF + doff) = z;
    }
    // prefetch A stage 0 (same cp.async group as T)
    copyA_stage(sb, 0, 0, ocg, tid);
    CP_COMMIT();

    int m0   = (wid & 3) * 32;
    int n0w  = (wid >> 2) * 64;
    int yrel = n0w >> 7;
    int x0w  = n0w & 127;
    int lr   = lane >> 2;
    int lj   = lane & 3;

    float acc[2][8][4];
    #pragma unroll
    for (int mt = 0; mt < 2; mt++)
        #pragma unroll
        for (int nt = 0; nt < 8; nt++)
            #pragma unroll
            for (int q = 0; q < 4; q++) acc[mt][nt][q] = 0.f;

    #pragma unroll 1
    for (int kst = 0; kst < 3; kst++) {
        int buf = kst & 1;
        CP_WAIT0();
        __syncthreads();
        if (kst < 2) { copyA_stage(sb, kst + 1, buf ^ 1, ocg, tid); CP_COMMIT(); }

        const char* As = smem + A_OFF + buf * A_STG;
        const char* Tr = smem + T_OFF + (yrel + kst) * 130 * PITCH;

        #pragma unroll
        for (int kw = 0; kw < 3; kw++) {
            const char* Ah = As + kw * A_TAP;
            const char* Tb = Tr + kw * PITCH;

            #pragma unroll
            for (int ks = 0; ks < 4; ks++) {
                int fo = ks * 32 + lj * 8;
                uint32_t ah[2][4];
                #pragma unroll
                for (int mt = 0; mt < 2; mt++) {
                    int r0 = (m0 + mt * 16 + lr) * PITCH + fo;
                    int r8 = r0 + 8 * PITCH;
                    uint2 w0 = *(const uint2*)(Ah + r0);
                    uint2 w8 = *(const uint2*)(Ah + r8);
                    ah[mt][0] = w0.x; ah[mt][2] = w0.y;
                    ah[mt][1] = w8.x; ah[mt][3] = w8.y;
                }
                #pragma unroll
                for (int nt = 0; nt < 8; nt++) {
                    int xo = (x0w + nt * 8 + lr) * PITCH + fo;
                    uint2 bv = *(const uint2*)(Tb + xo);
                    mma16816(acc[0][nt], ah[0][0], ah[0][1], ah[0][2], ah[0][3], bv.x, bv.y);
                    mma16816(acc[1][nt], ah[1][0], ah[1][1], ah[1][2], ah[1][3], bv.x, bv.y);
                }
            }
        }
    }

    // epilogue: masked stores
    int y = y0 + yrel;
    #pragma unroll
    for (int mt = 0; mt < 2; mt++) {
        int mrow = m0 + mt * 16 + lr;
        float mk0 = smask[mrow];
        float mk1 = smask[mrow + 8];
        int oc0 = ocg * 128 + mrow;
        size_t b0 = ((size_t)(img * OCH + oc0) * HW + y) * HW;
        size_t b1 = b0 + (size_t)8 * HW * HW;
        #pragma unroll
        for (int nt = 0; nt < 8; nt++) {
            int xcol = x0w + nt * 8 + lj * 2;
            float2 v0 = { acc[mt][nt][0] * mk0, acc[mt][nt][1] * mk0 };
            float2 v1 = { acc[mt][nt][2] * mk1, acc[mt][nt][3] * mk1 };
            *(float2*)(out + b0 + xcol) = v0;
            *(float2*)(out + b1 + xcol) = v1;
        }
    }
}

// ---------------- launch ----------------
extern "C" void kernel_launch(void* const* d_in, const int* in_sizes, int n_in,
                              void* d_out, int out_size) {
    const float* x = (const float*)d_in[0];   // [32,64,128,128]
    const float* w = (const float*)d_in[1];   // [256,64,3,3]
    const float* a = (const float*)d_in[2];   // [8,67,3,3]
    const float* b = (const float*)d_in[3];   // [8]
    float* out = (float*)d_out;               // [32,256,128,128]

    cudaFuncSetAttribute(conv_mma_kernel,
                         cudaFuncAttributeMaxDynamicSharedMemorySize, SMEM_CONV);

    zero_hist_kernel<<<16, 256>>>();
    norms_kernel<<<1, 256>>>(w);
    kbuckets_kernel<<<256, 256>>>(w, a, b);
    wprep_kernel<<<576, 256>>>(w);
    xprep_kernel<<<dim3(HW, NB), 256>>>(x);
    vote_kernel<<<dim3(4, 8, NB), 256>>>(x, a, b);
    argmax_kernel<<<1, 256>>>();
    mask_kernel<<<1, 256>>>();
    conv_mma_kernel<<<dim3(2, 64, NB), 512, SMEM_CONV>>>(out);
}